// round 4
// baseline (speedup 1.0000x reference)
#include <cuda_runtime.h>

// Inputs (metadata order; reference int64 narrowed to int32 by harness):
//   d_in[0]: y      float32 (T, B, 7)
//   d_in[1]: t      int32   (T, B, 3)
//   d_in[2]: y_len  int32   (B,)
// Output: float32 scalar
//
// One thread = 4 consecutive b at one timestep t.
// y rows for the group: 7x float4 (112B contiguous, 16B aligned).
// Each float4 is predicated on the liveness of the 1-2 samples it covers,
// so dead sectors are never fetched (sector-granular traffic saving).

#define TPB 256

__global__ void zero_out_kernel(float* out) {
    if (threadIdx.x == 0) out[0] = 0.0f;
}

__device__ __forceinline__ float ce_row(float l0, float l1, float l2,
                                        float l3, float l4,
                                        float l5, float l6,
                                        int c0, int c1, int c2)
{
    float m0 = fmaxf(l0, fmaxf(l1, l2));
    float s0 = __expf(l0 - m0) + __expf(l1 - m0) + __expf(l2 - m0);
    float sel0 = (c0 == 0) ? l0 : ((c0 == 1) ? l1 : l2);
    float r = m0 + __logf(s0) - sel0;

    float m1 = fmaxf(l3, l4);
    float s1 = __expf(l3 - m1) + __expf(l4 - m1);
    r += m1 + __logf(s1) - ((c1 == 0) ? l3 : l4);

    float m2 = fmaxf(l5, l6);
    float s2 = __expf(l5 - m2) + __expf(l6 - m2);
    r += m2 + __logf(s2) - ((c2 == 0) ? l5 : l6);
    return r;
}

__device__ __forceinline__ float4 ldg4_pred(const float4* p, bool pred) {
    return pred ? __ldg(p) : make_float4(0.f, 0.f, 0.f, 0.f);
}
__device__ __forceinline__ int4 ldgi4_pred(const int4* p, bool pred) {
    return pred ? __ldg(p) : make_int4(0, 0, 0, 0);
}

__global__ __launch_bounds__(TPB)
void ce_loss_kernel(const float4* __restrict__ y4,
                    const int4* __restrict__ t4,
                    const int4* __restrict__ len4,
                    float* __restrict__ out,
                    int T, int B)
{
    const int BG  = B >> 2;
    const int tid = blockIdx.x * TPB + threadIdx.x;
    const int t   = tid / BG;
    const int bg  = tid - t * BG;

    float contrib = 0.0f;

    const int4 L = len4[bg];   // lengths for b0..b3 (cached in L1/L2)

    const bool a0 = (t < T) && (t < L.x);
    const bool a1 = (t < T) && (t < L.y);
    const bool a2 = (t < T) && (t < L.z);
    const bool a3 = (t < T) && (t < L.w);

    if (a0 | a1 | a2 | a3) {
        const long long e = (long long)t * B + (bg << 2);
        const long long q = e >> 2;
        const float4* yb = y4 + q * 7;
        const int4*   tb = t4 + q * 3;

        // per-sector predication: each load fetched only if a covering sample lives
        float4 v0 = ldg4_pred(yb + 0, a0);        // b0
        float4 v1 = ldg4_pred(yb + 1, a0 | a1);   // b0 | b1
        float4 v2 = ldg4_pred(yb + 2, a1);        // b1
        float4 v3 = ldg4_pred(yb + 3, a1 | a2);   // b1 | b2
        float4 v4 = ldg4_pred(yb + 4, a2);        // b2
        float4 v5 = ldg4_pred(yb + 5, a2 | a3);   // b2 | b3
        float4 v6 = ldg4_pred(yb + 6, a3);        // b3
        int4 i0 = ldgi4_pred(tb + 0, a0 | a1);
        int4 i1 = ldgi4_pred(tb + 1, a1 | a2);
        int4 i2 = ldgi4_pred(tb + 2, a2 | a3);

        if (a0)
            contrib += __fdividef(
                ce_row(v0.x, v0.y, v0.z, v0.w, v1.x, v1.y, v1.z,
                       i0.x, i0.y, i0.z), (float)L.x);
        if (a1)
            contrib += __fdividef(
                ce_row(v1.w, v2.x, v2.y, v2.z, v2.w, v3.x, v3.y,
                       i0.w, i1.x, i1.y), (float)L.y);
        if (a2)
            contrib += __fdividef(
                ce_row(v3.z, v3.w, v4.x, v4.y, v4.z, v4.w, v5.x,
                       i1.z, i1.w, i2.x), (float)L.z);
        if (a3)
            contrib += __fdividef(
                ce_row(v5.y, v5.z, v5.w, v6.x, v6.y, v6.z, v6.w,
                       i2.y, i2.z, i2.w), (float)L.w);
    }

    // warp reduce
    #pragma unroll
    for (int off = 16; off > 0; off >>= 1)
        contrib += __shfl_down_sync(0xFFFFFFFFu, contrib, off);

    __shared__ float wsum[TPB / 32];
    const int lane = threadIdx.x & 31;
    const int wid  = threadIdx.x >> 5;
    if (lane == 0) wsum[wid] = contrib;
    __syncthreads();

    if (threadIdx.x < TPB / 32) {
        float v = wsum[threadIdx.x];
        #pragma unroll
        for (int off = (TPB / 64); off > 0; off >>= 1)
            v += __shfl_down_sync(0xFFu, v, off);
        if (threadIdx.x == 0 && v != 0.0f)
            atomicAdd(out, v * (1.0f / (float)B));
    }
}

extern "C" void kernel_launch(void* const* d_in, const int* in_sizes, int n_in,
                              void* d_out, int out_size)
{
    const float4* y4   = (const float4*)d_in[0];
    const int4*   t4   = (const int4*)d_in[1];
    const int4*   len4 = (const int4*)d_in[2];
    float* out = (float*)d_out;

    const int B = in_sizes[2];                 // 512
    const int T = in_sizes[0] / (B * 7);       // 4096
    const int BG = B >> 2;                     // 128

    zero_out_kernel<<<1, 32>>>(out);

    const long long total = (long long)T * BG; // 524288
    const int nblocks = (int)((total + TPB - 1) / TPB);
    ce_loss_kernel<<<nblocks, TPB>>>(y4, t4, len4, out, T, B);
}